// round 3
// baseline (speedup 1.0000x reference)
#include <cuda_runtime.h>
#include <math.h>
#include <stdint.h>

#define D 128
#define MAXN 2097152              // 2^21 >= 2,000,000 ; index fits in 21 bits
#define MAIN_BLOCKS 1184          // 8 CTAs/SM * 148 SMs
#define MAIN_THREADS 256
#define CAND_CAP 4096
#define ACC_BLOCKS 64

// ---------------- device scratch (no allocations allowed) ----------------
__device__ float               g_y[MAXN];
__device__ unsigned            g_h1[2048];
__device__ double              g_inv_len;
__device__ float               g_inv_lenf;
__device__ unsigned            g_keyfloor;
__device__ int                 g_kk;
__device__ int                 g_candcnt;
__device__ int                 g_candidx[CAND_CAP];
__device__ unsigned long long  g_candkey[CAND_CAP];
__device__ int                 g_selidx[CAND_CAP];
__device__ float               g_selgate[CAND_CAP];
__device__ int                 g_selcnt;
__device__ float               g_partial[ACC_BLOCKS][D];
__device__ unsigned            g_done;

// monotonic key: larger float -> larger unsigned
__device__ __forceinline__ unsigned fkey(float f) {
    unsigned u = __float_as_uint(f);
    return (u & 0x80000000u) ? ~u : (u | 0x80000000u);
}

// ---------------- K0: init + ||v|| ----------------
__global__ void k_init(const float* __restrict__ v) {
    __shared__ double sv[D];
    int t = threadIdx.x;
    for (int i = t; i < 2048; i += blockDim.x) g_h1[i] = 0u;
    if (t == 0) { g_candcnt = 0; g_selcnt = 0; g_done = 0u; }
    if (t < D) { double x = (double)v[t]; sv[t] = x * x; }
    __syncthreads();
    if (t == 0) {
        double s = 0.0;
        for (int i = 0; i < D; i++) s += sv[i];
        double inv = 1.0 / sqrt(s);
        g_inv_len  = inv;
        g_inv_lenf = (float)inv;
    }
}

// ---------------- K1: scores + 2048-bucket histogram ----------------
// Each warp handles 8 CONSECUTIVE rows per iteration (4KB contiguous span,
// 8 front-batched independent loads). Full xor-reduce puts every row-sum on
// all lanes; lanes 0..7 each commit one row (coalesced g_y store, parallel
// smem atomics).
__global__ void __launch_bounds__(MAIN_THREADS) k_main(
    const float* __restrict__ x, const float* __restrict__ v, int N)
{
    __shared__ unsigned sh[2048];
    for (int i = threadIdx.x; i < 2048; i += blockDim.x) sh[i] = 0u;

    const int lane = threadIdx.x & 31;
    const float4 v4 = __ldg(((const float4*)v) + lane);
    const float invf = g_inv_lenf;
    __syncthreads();

    const int warp = blockIdx.x * (blockDim.x >> 5) + (threadIdx.x >> 5);
    const int nw   = gridDim.x * (blockDim.x >> 5);

    for (int base = warp * 8; base < N; base += nw * 8) {
        float s[8];
#pragma unroll
        for (int u = 0; u < 8; u++) {
            const int r = base + u;
            s[u] = 0.f;
            if (r < N) {
                float4 a = __ldcs((const float4*)(x + (size_t)r * D) + lane);
                float t = a.x * v4.x;
                t = fmaf(a.y, v4.y, t);
                t = fmaf(a.z, v4.z, t);
                t = fmaf(a.w, v4.w, t);
                s[u] = t;
            }
        }
#pragma unroll
        for (int o = 16; o; o >>= 1) {
#pragma unroll
            for (int u = 0; u < 8; u++)
                s[u] += __shfl_xor_sync(0xffffffffu, s[u], o);
        }
        if (lane < 8) {
            // static 8-way select (predicated moves, no spill)
            float my = s[0];
            if (lane == 1) my = s[1];
            if (lane == 2) my = s[2];
            if (lane == 3) my = s[3];
            if (lane == 4) my = s[4];
            if (lane == 5) my = s[5];
            if (lane == 6) my = s[6];
            if (lane == 7) my = s[7];
            const int r = base + lane;
            if (r < N) {
                float y = my * invf;
                g_y[r] = y;
                atomicAdd(&sh[fkey(y) >> 21], 1u);
            }
        }
    }
    __syncthreads();
    for (int i = threadIdx.x; i < 2048; i += blockDim.x) {
        unsigned c = sh[i];
        if (c) atomicAdd(&g_h1[i], c);
    }
}

// ---------------- K2: parallel suffix scan of histogram -> bucket floor ---
__global__ void __launch_bounds__(256) k_scan(const int* __restrict__ kp, int N) {
    __shared__ unsigned ps[256];
    const int t = threadIdx.x;

    int kk = *kp;
    if (kk > N) kk = N;
    if (kk < 1) kk = 1;

    unsigned loc[8];
    unsigned sum = 0;
#pragma unroll
    for (int i = 0; i < 8; i++) {
        loc[i] = g_h1[2047 - (t * 8 + i)];
        sum += loc[i];
    }
    ps[t] = sum;
    __syncthreads();
    for (int off = 1; off < 256; off <<= 1) {
        unsigned add = (t >= off) ? ps[t - off] : 0u;
        __syncthreads();
        ps[t] += add;
        __syncthreads();
    }
    unsigned base = (t == 0) ? 0u : ps[t - 1];
    if (base < (unsigned)kk && ps[t] >= (unsigned)kk) {
        unsigned cum = base;
        int b = 0;
#pragma unroll
        for (int i = 0; i < 8; i++) {
            cum += loc[i];
            if (cum >= (unsigned)kk) { b = 2047 - (t * 8 + i); break; }
        }
        g_keyfloor = (unsigned)b << 21;
        g_kk = kk;
    }
    if (t == 0 && ps[255] < (unsigned)kk) {
        g_keyfloor = 0u;
        g_kk = kk;
    }
}

// ---------------- K3: collect candidates (vectorized) --------------------
__global__ void k_cand(int N) {
    const unsigned kf = g_keyfloor;
    const int N4 = N >> 2;
    const float4* y4 = (const float4*)g_y;
    for (int i = blockIdx.x * blockDim.x + threadIdx.x; i < N4;
         i += gridDim.x * blockDim.x) {
        float4 a = y4[i];
        if (fkey(a.x) >= kf) { int p = atomicAdd(&g_candcnt, 1); if (p < CAND_CAP) g_candidx[p] = 4 * i; }
        if (fkey(a.y) >= kf) { int p = atomicAdd(&g_candcnt, 1); if (p < CAND_CAP) g_candidx[p] = 4 * i + 1; }
        if (fkey(a.z) >= kf) { int p = atomicAdd(&g_candcnt, 1); if (p < CAND_CAP) g_candidx[p] = 4 * i + 2; }
        if (fkey(a.w) >= kf) { int p = atomicAdd(&g_candcnt, 1); if (p < CAND_CAP) g_candidx[p] = 4 * i + 3; }
    }
    // tail
    if (blockIdx.x == 0 && threadIdx.x < 4) {
        int i = (N4 << 2) + threadIdx.x;
        if (i < N && fkey(g_y[i]) >= kf) {
            int p = atomicAdd(&g_candcnt, 1);
            if (p < CAND_CAP) g_candidx[p] = i;
        }
    }
}

// ---------------- K4: fp64 refine of candidate scores, pack sort keys ----
__global__ void k_refine(const float* __restrict__ x, const float* __restrict__ v) {
    const int lane = threadIdx.x & 31;
    const int w    = blockIdx.x * (blockDim.x >> 5) + (threadIdx.x >> 5);
    const int nw   = gridDim.x * (blockDim.x >> 5);
    int nc = g_candcnt;
    if (nc > CAND_CAP) nc = CAND_CAP;
    const double inv = g_inv_len;
    const float4 v4 = __ldg(((const float4*)v) + lane);

    for (int j = w; j < nc; j += nw) {
        const int r = g_candidx[j];
        float4 a = __ldg((const float4*)(x + (size_t)r * D) + lane);
        double s = (double)a.x * (double)v4.x
                 + (double)a.y * (double)v4.y
                 + (double)a.z * (double)v4.z
                 + (double)a.w * (double)v4.w;
#pragma unroll
        for (int o = 16; o; o >>= 1) s += __shfl_down_sync(0xffffffffu, s, o);
        if (lane == 0) {
            double yd = s * inv;
            long long bl = __double_as_longlong(yd);
            unsigned long long u = (unsigned long long)bl;
            unsigned long long m = (u >> 63) ? ~u : (u | 0x8000000000000000ull);
            unsigned long long key = (m & ~0x1FFFFFull)
                                   | (unsigned long long)(0x1FFFFFu - (unsigned)r);
            g_candkey[j] = key;
        }
    }
}

// ---------------- K5: single-block bitonic sort (descending), top-k ------
__global__ void __launch_bounds__(1024) k_sort() {
    __shared__ unsigned long long sk[CAND_CAP];
    int nc = g_candcnt; if (nc > CAND_CAP) nc = CAND_CAP;
    int kk = g_kk;      if (kk > nc) kk = nc;

    for (int i = threadIdx.x; i < CAND_CAP; i += blockDim.x)
        sk[i] = (i < nc) ? g_candkey[i] : 0ull;
    __syncthreads();

    for (int k2 = 2; k2 <= CAND_CAP; k2 <<= 1) {
        for (int j = k2 >> 1; j > 0; j >>= 1) {
            for (int i = threadIdx.x; i < CAND_CAP; i += blockDim.x) {
                int ixj = i ^ j;
                if (ixj > i) {
                    unsigned long long a = sk[i], b = sk[ixj];
                    bool swp = ((i & k2) == 0) ? (a < b) : (a > b);  // descending
                    if (swp) { sk[i] = b; sk[ixj] = a; }
                }
            }
            __syncthreads();
        }
    }
    for (int i = threadIdx.x; i < kk; i += blockDim.x) {
        unsigned long long key = sk[i];
        int idx = 0x1FFFFF - (int)(key & 0x1FFFFFull);
        g_selidx[i] = idx;
        float y = g_y[idx];
        g_selgate[i] = 1.f / (1.f + expf(-y));
    }
    if (threadIdx.x == 0) g_selcnt = kk;
}

// ---------------- K6: gather-reduce + fused final reduce ------------------
__global__ void __launch_bounds__(D) k_acc(const float* __restrict__ x,
                                           float* __restrict__ out) {
    __shared__ bool last;
    const int c  = threadIdx.x;
    const int kk = g_selcnt;
    const int per = (kk + gridDim.x - 1) / (int)gridDim.x;
    int j0 = blockIdx.x * per;
    int j1 = j0 + per; if (j1 > kk) j1 = kk;
    float acc = 0.f;
    for (int j = j0; j < j1; ++j) {
        acc = fmaf(g_selgate[j], __ldg(x + (size_t)g_selidx[j] * D + c), acc);
    }
    g_partial[blockIdx.x][c] = acc;
    __threadfence();
    if (c == 0) last = (atomicAdd(&g_done, 1u) == (unsigned)(gridDim.x - 1));
    __syncthreads();
    if (last) {
        float s = 0.f;
        for (int b = 0; b < ACC_BLOCKS; ++b) s += g_partial[b][c];
        out[c] = s;
    }
}

// ---------------- launch ----------------
extern "C" void kernel_launch(void* const* d_in, const int* in_sizes, int n_in,
                              void* d_out, int out_size) {
    const float* x  = (const float*)d_in[0];
    const float* v  = (const float*)d_in[1];
    const int*   kp = (const int*)d_in[2];
    float* out = (float*)d_out;
    int N = in_sizes[0] / D;
    if (N > MAXN) N = MAXN;

    k_init  <<<1, 256>>>(v);
    k_main  <<<MAIN_BLOCKS, MAIN_THREADS>>>(x, v, N);
    k_scan  <<<1, 256>>>(kp, N);
    k_cand  <<<512, 256>>>(N);
    k_refine<<<128, 256>>>(x, v);
    k_sort  <<<1, 1024>>>();
    k_acc   <<<ACC_BLOCKS, D>>>(x, out);
    (void)n_in; (void)out_size;
}

// round 4
// speedup vs baseline: 1.0841x; 1.0841x over previous
#include <cuda_runtime.h>
#include <math.h>
#include <stdint.h>

#define D 128
#define MAXN 2097152              // 2^21 >= 2,000,000 ; index fits in 21 bits
#define MAIN_BLOCKS 1184          // 8 CTAs/SM * 148 SMs
#define MAIN_THREADS 256
#define CAND_CAP 4096
#define ACC_BLOCKS 64

// ---------------- device scratch (no allocations allowed) ----------------
__device__ float               g_y[MAXN];
__device__ unsigned            g_h1[2048];
__device__ double              g_inv_len;
__device__ float               g_inv_lenf;
__device__ unsigned            g_keyfloor;
__device__ int                 g_kk;
__device__ int                 g_candcnt;
__device__ int                 g_candidx[CAND_CAP];
__device__ unsigned long long  g_candkey[CAND_CAP];
__device__ int                 g_selidx[CAND_CAP];
__device__ float               g_selgate[CAND_CAP];
__device__ int                 g_selcnt;
__device__ float               g_partial[ACC_BLOCKS][D];
__device__ unsigned            g_done;

// monotonic key: larger float -> larger unsigned
__device__ __forceinline__ unsigned fkey(float f) {
    unsigned u = __float_as_uint(f);
    return (u & 0x80000000u) ? ~u : (u | 0x80000000u);
}

// ---------------- K0: init + ||v|| ----------------
__global__ void k_init(const float* __restrict__ v) {
    __shared__ double sv[D];
    int t = threadIdx.x;
    for (int i = t; i < 2048; i += blockDim.x) g_h1[i] = 0u;
    if (t == 0) { g_candcnt = 0; g_selcnt = 0; g_done = 0u; }
    if (t < D) { double x = (double)v[t]; sv[t] = x * x; }
    __syncthreads();
    if (t == 0) {
        double s = 0.0;
        for (int i = 0; i < D; i++) s += sv[i];
        double inv = 1.0 / sqrt(s);
        g_inv_len  = inv;
        g_inv_lenf = (float)inv;
    }
}

// ---------------- K1: scores + 2048-bucket histogram (R2-proven form) ----
__global__ void __launch_bounds__(MAIN_THREADS) k_main(
    const float* __restrict__ x, const float* __restrict__ v, int N)
{
    __shared__ unsigned sh[2048];
    for (int i = threadIdx.x; i < 2048; i += blockDim.x) sh[i] = 0u;

    const int lane = threadIdx.x & 31;
    const float4 v4 = __ldg(((const float4*)v) + lane);
    const float invf = g_inv_lenf;
    __syncthreads();

    const int warp = blockIdx.x * (blockDim.x >> 5) + (threadIdx.x >> 5);
    const int nw   = gridDim.x * (blockDim.x >> 5);

    for (int r = warp; r < N; r += 4 * nw) {
        const int r1 = r + nw, r2 = r + 2 * nw, r3 = r + 3 * nw;
        float s0 = 0.f, s1 = 0.f, s2 = 0.f, s3 = 0.f;
        {
            float4 a = __ldcs((const float4*)(x + (size_t)r * D) + lane);
            s0 = a.x * v4.x; s0 = fmaf(a.y, v4.y, s0);
            s0 = fmaf(a.z, v4.z, s0); s0 = fmaf(a.w, v4.w, s0);
        }
        if (r1 < N) {
            float4 a = __ldcs((const float4*)(x + (size_t)r1 * D) + lane);
            s1 = a.x * v4.x; s1 = fmaf(a.y, v4.y, s1);
            s1 = fmaf(a.z, v4.z, s1); s1 = fmaf(a.w, v4.w, s1);
        }
        if (r2 < N) {
            float4 a = __ldcs((const float4*)(x + (size_t)r2 * D) + lane);
            s2 = a.x * v4.x; s2 = fmaf(a.y, v4.y, s2);
            s2 = fmaf(a.z, v4.z, s2); s2 = fmaf(a.w, v4.w, s2);
        }
        if (r3 < N) {
            float4 a = __ldcs((const float4*)(x + (size_t)r3 * D) + lane);
            s3 = a.x * v4.x; s3 = fmaf(a.y, v4.y, s3);
            s3 = fmaf(a.z, v4.z, s3); s3 = fmaf(a.w, v4.w, s3);
        }
#pragma unroll
        for (int o = 16; o; o >>= 1) {
            s0 += __shfl_down_sync(0xffffffffu, s0, o);
            s1 += __shfl_down_sync(0xffffffffu, s1, o);
            s2 += __shfl_down_sync(0xffffffffu, s2, o);
            s3 += __shfl_down_sync(0xffffffffu, s3, o);
        }
        if (lane == 0) {
            float y0 = s0 * invf;
            g_y[r] = y0; atomicAdd(&sh[fkey(y0) >> 21], 1u);
            if (r1 < N) { float y = s1 * invf; g_y[r1] = y; atomicAdd(&sh[fkey(y) >> 21], 1u); }
            if (r2 < N) { float y = s2 * invf; g_y[r2] = y; atomicAdd(&sh[fkey(y) >> 21], 1u); }
            if (r3 < N) { float y = s3 * invf; g_y[r3] = y; atomicAdd(&sh[fkey(y) >> 21], 1u); }
        }
    }
    __syncthreads();
    for (int i = threadIdx.x; i < 2048; i += blockDim.x) {
        unsigned c = sh[i];
        if (c) atomicAdd(&g_h1[i], c);
    }
}

// ---------------- K2: parallel suffix scan of histogram -> bucket floor ---
__global__ void __launch_bounds__(256) k_scan(const int* __restrict__ kp, int N) {
    __shared__ unsigned ps[256];
    const int t = threadIdx.x;

    int kk = *kp;
    if (kk > N) kk = N;
    if (kk < 1) kk = 1;

    unsigned loc[8];
    unsigned sum = 0;
#pragma unroll
    for (int i = 0; i < 8; i++) {
        loc[i] = g_h1[2047 - (t * 8 + i)];
        sum += loc[i];
    }
    ps[t] = sum;
    __syncthreads();
    for (int off = 1; off < 256; off <<= 1) {
        unsigned add = (t >= off) ? ps[t - off] : 0u;
        __syncthreads();
        ps[t] += add;
        __syncthreads();
    }
    unsigned base = (t == 0) ? 0u : ps[t - 1];
    if (base < (unsigned)kk && ps[t] >= (unsigned)kk) {
        unsigned cum = base;
        int b = 0;
#pragma unroll
        for (int i = 0; i < 8; i++) {
            cum += loc[i];
            if (cum >= (unsigned)kk) { b = 2047 - (t * 8 + i); break; }
        }
        g_keyfloor = (unsigned)b << 21;
        g_kk = kk;
    }
    if (t == 0 && ps[255] < (unsigned)kk) {
        g_keyfloor = 0u;
        g_kk = kk;
    }
}

// ---------------- K3: collect candidates (vectorized, wide grid) ---------
__global__ void k_cand(int N) {
    const unsigned kf = g_keyfloor;
    const int N4 = N >> 2;
    const float4* y4 = (const float4*)g_y;
    for (int i = blockIdx.x * blockDim.x + threadIdx.x; i < N4;
         i += gridDim.x * blockDim.x) {
        float4 a = y4[i];
        if (fkey(a.x) >= kf) { int p = atomicAdd(&g_candcnt, 1); if (p < CAND_CAP) g_candidx[p] = 4 * i; }
        if (fkey(a.y) >= kf) { int p = atomicAdd(&g_candcnt, 1); if (p < CAND_CAP) g_candidx[p] = 4 * i + 1; }
        if (fkey(a.z) >= kf) { int p = atomicAdd(&g_candcnt, 1); if (p < CAND_CAP) g_candidx[p] = 4 * i + 2; }
        if (fkey(a.w) >= kf) { int p = atomicAdd(&g_candcnt, 1); if (p < CAND_CAP) g_candidx[p] = 4 * i + 3; }
    }
    // tail
    if (blockIdx.x == 0 && threadIdx.x < 4) {
        int i = (N4 << 2) + threadIdx.x;
        if (i < N && fkey(g_y[i]) >= kf) {
            int p = atomicAdd(&g_candcnt, 1);
            if (p < CAND_CAP) g_candidx[p] = i;
        }
    }
}

// ---------------- K4: fp64 refine of candidate scores, pack sort keys ----
__global__ void k_refine(const float* __restrict__ x, const float* __restrict__ v) {
    const int lane = threadIdx.x & 31;
    const int w    = blockIdx.x * (blockDim.x >> 5) + (threadIdx.x >> 5);
    const int nw   = gridDim.x * (blockDim.x >> 5);
    int nc = g_candcnt;
    if (nc > CAND_CAP) nc = CAND_CAP;
    const double inv = g_inv_len;
    const float4 v4 = __ldg(((const float4*)v) + lane);

    for (int j = w; j < nc; j += nw) {
        const int r = g_candidx[j];
        float4 a = __ldg((const float4*)(x + (size_t)r * D) + lane);
        double s = (double)a.x * (double)v4.x
                 + (double)a.y * (double)v4.y
                 + (double)a.z * (double)v4.z
                 + (double)a.w * (double)v4.w;
#pragma unroll
        for (int o = 16; o; o >>= 1) s += __shfl_down_sync(0xffffffffu, s, o);
        if (lane == 0) {
            double yd = s * inv;
            long long bl = __double_as_longlong(yd);
            unsigned long long u = (unsigned long long)bl;
            unsigned long long m = (u >> 63) ? ~u : (u | 0x8000000000000000ull);
            unsigned long long key = (m & ~0x1FFFFFull)
                                   | (unsigned long long)(0x1FFFFFu - (unsigned)r);
            g_candkey[j] = key;
        }
    }
}

// ---------------- K5: single-block bitonic sort (descending), top-k ------
__global__ void __launch_bounds__(1024) k_sort() {
    __shared__ unsigned long long sk[CAND_CAP];
    int nc = g_candcnt; if (nc > CAND_CAP) nc = CAND_CAP;
    int kk = g_kk;      if (kk > nc) kk = nc;

    for (int i = threadIdx.x; i < CAND_CAP; i += blockDim.x)
        sk[i] = (i < nc) ? g_candkey[i] : 0ull;
    __syncthreads();

    for (int k2 = 2; k2 <= CAND_CAP; k2 <<= 1) {
        for (int j = k2 >> 1; j > 0; j >>= 1) {
            for (int i = threadIdx.x; i < CAND_CAP; i += blockDim.x) {
                int ixj = i ^ j;
                if (ixj > i) {
                    unsigned long long a = sk[i], b = sk[ixj];
                    bool swp = ((i & k2) == 0) ? (a < b) : (a > b);  // descending
                    if (swp) { sk[i] = b; sk[ixj] = a; }
                }
            }
            __syncthreads();
        }
    }
    for (int i = threadIdx.x; i < kk; i += blockDim.x) {
        unsigned long long key = sk[i];
        int idx = 0x1FFFFF - (int)(key & 0x1FFFFFull);
        g_selidx[i] = idx;
        float y = g_y[idx];
        g_selgate[i] = 1.f / (1.f + expf(-y));
    }
    if (threadIdx.x == 0) g_selcnt = kk;
}

// ---------------- K6: gather-reduce + fused final reduce ------------------
__global__ void __launch_bounds__(D) k_acc(const float* __restrict__ x,
                                           float* __restrict__ out) {
    __shared__ bool last;
    const int c  = threadIdx.x;
    const int kk = g_selcnt;
    const int per = (kk + gridDim.x - 1) / (int)gridDim.x;
    int j0 = blockIdx.x * per;
    int j1 = j0 + per; if (j1 > kk) j1 = kk;
    float acc = 0.f;
    for (int j = j0; j < j1; ++j) {
        acc = fmaf(g_selgate[j], __ldg(x + (size_t)g_selidx[j] * D + c), acc);
    }
    g_partial[blockIdx.x][c] = acc;
    __threadfence();
    if (c == 0) last = (atomicAdd(&g_done, 1u) == (unsigned)(gridDim.x - 1));
    __syncthreads();
    if (last) {
        float s = 0.f;
        for (int b = 0; b < ACC_BLOCKS; ++b) s += g_partial[b][c];
        out[c] = s;
    }
}

// ---------------- launch ----------------
extern "C" void kernel_launch(void* const* d_in, const int* in_sizes, int n_in,
                              void* d_out, int out_size) {
    const float* x  = (const float*)d_in[0];
    const float* v  = (const float*)d_in[1];
    const int*   kp = (const int*)d_in[2];
    float* out = (float*)d_out;
    int N = in_sizes[0] / D;
    if (N > MAXN) N = MAXN;

    k_init  <<<1, 256>>>(v);
    k_main  <<<MAIN_BLOCKS, MAIN_THREADS>>>(x, v, N);
    k_scan  <<<1, 256>>>(kp, N);
    k_cand  <<<2048, 256>>>(N);
    k_refine<<<128, 256>>>(x, v);
    k_sort  <<<1, 1024>>>();
    k_acc   <<<ACC_BLOCKS, D>>>(x, out);
    (void)n_in; (void)out_size;
}